// round 13
// baseline (speedup 1.0000x reference)
#include <cuda_runtime.h>
#include <cstdint>

// FWHT over rows of length 4096: H4096 = H2^{⊗12}.  FINAL (converged).
// 128 threads/CTA, 32 elements/thread, one row per CTA.
// Rounds: A = bits {0,1,9,10,11} (register, from 8 coalesced LDG.128),
//         B = bits {2,3,4}   (float4-granular smem exchange),
//         C = bits {5,6,7,8} (float2-granular smem exchange), then store.
// Swizzle on float4-index F' = F ^ ((F>>3)&7): conflict-free for all three
// smem patterns (verified per 8/16-lane phase), alignment-preserving.
// 56 regs / 9 CTAs/SM is the measured optimum: all 8 LDG.128 destinations
// concurrently live (full per-thread MLP). 40-reg cap serializes the load
// stream (DRAM 79%->64%); higher occupancy buys nothing; shuffle-based or
// float4-granular round C are provably worse at this thread count.
// Measured at the B300 LTS path-independent throughput cap:
// DRAM 80.2%, 6354 GB/s, ncu 75.4 us.

#define FWHT_N 4096
#define FWHT_THREADS 128

// physical float4 index
__device__ __forceinline__ int swz4(int F) { return F ^ ((F >> 3) & 7); }

__device__ __forceinline__ float4 v4add(float4 a, float4 b) {
    return make_float4(a.x + b.x, a.y + b.y, a.z + b.z, a.w + b.w);
}
__device__ __forceinline__ float4 v4sub(float4 a, float4 b) {
    return make_float4(a.x - b.x, a.y - b.y, a.z - b.z, a.w - b.w);
}

// H8 butterfly across 8 float4 registers (componentwise).
__device__ __forceinline__ void fwht_h8_vec(float4* v) {
#pragma unroll
    for (int h = 1; h < 8; h <<= 1) {
#pragma unroll
        for (int s = 0; s < 8; s += 2 * h) {
#pragma unroll
            for (int k = 0; k < h; k++) {
                float4 a = v[s + k];
                float4 b = v[s + k + h];
                v[s + k]     = v4add(a, b);
                v[s + k + h] = v4sub(a, b);
            }
        }
    }
}

// H4 inside one float4 (element bits {0,1}).
__device__ __forceinline__ float4 fwht_h4_in(float4 a) {
    float x0 = a.x + a.y, x1 = a.x - a.y;
    float x2 = a.z + a.w, x3 = a.z - a.w;
    return make_float4(x0 + x2, x1 + x3, x0 - x2, x1 - x3);
}

__global__ void __launch_bounds__(FWHT_THREADS)
fwht4096_kernel(const float* __restrict__ x,
                const float* __restrict__ scale,
                float* __restrict__ out)
{
    __shared__ float4 S4[FWHT_N / 4];
    float2* S2 = reinterpret_cast<float2*>(S4);

    const int row = blockIdx.x;
    const int t   = threadIdx.x;   // 0..127

    const float4* xr  = reinterpret_cast<const float4*>(x)  + (size_t)row * (FWHT_N / 4);
    float2*       or2 = reinterpret_cast<float2*>(out)      + (size_t)row * (FWHT_N / 2);

    float4 v[8];

    // ---- load: v[j] = x[row, 512j + 4t .. +3]   (8 coalesced LDG.128)
    // elem i = 4t + 512j + k : k->bits{0,1}, t->bits{2..8}, j->bits{9,10,11}
#pragma unroll
    for (int j = 0; j < 8; j++)
        v[j] = __ldcs(&xr[128 * j + t]);

    // ---- round A: H8 across j (bits 9..11) ⊗ H4 in-vector (bits 0,1)
    fwht_h8_vec(v);
#pragma unroll
    for (int j = 0; j < 8; j++)
        v[j] = fwht_h4_in(v[j]);

    // ---- exchange 1: logical float4-idx F = t + 128j
#pragma unroll
    for (int j = 0; j < 8; j++)
        S4[swz4(t + 128 * j)] = v[j];
    __syncthreads();

    // ---- round B: H8 over elem bits {2,3,4}
    // logical F = m | ((t&7)<<3) | ((t>>3)<<6), m = elem bits {2,3,4}
    {
        const int Fb = ((t & 7) << 3) | ((t >> 3) << 6);
#pragma unroll
        for (int m = 0; m < 8; m++)
            v[m] = S4[swz4(Fb | m)];

        fwht_h8_vec(v);   // butterfly across m

#pragma unroll
        for (int m = 0; m < 8; m++)
            S4[swz4(Fb | m)] = v[m];
    }
    __syncthreads();

    // ---- round C: H16 over elem bits {5,6,7,8} at float2 granularity
    // logical float2-idx g = (n<<4) | (t&15) | ((t>>4)<<8), n = elem bits {5..8}
    {
        const int gb = (t & 15) | ((t >> 4) << 8);
        float2 w[16];
#pragma unroll
        for (int n = 0; n < 16; n++) {
            int g = gb | (n << 4);
            w[n] = S2[(swz4(g >> 1) << 1) | (g & 1)];
        }

#pragma unroll
        for (int h = 1; h < 16; h <<= 1) {
#pragma unroll
            for (int s = 0; s < 16; s += 2 * h) {
#pragma unroll
                for (int k = 0; k < h; k++) {
                    float2 a = w[s + k];
                    float2 b = w[s + k + h];
                    w[s + k]     = make_float2(a.x + b.x, a.y + b.y);
                    w[s + k + h] = make_float2(a.x - b.x, a.y - b.y);
                }
            }
        }

        const float sc = *scale;
        // store: global float2-idx g (coalesced per-warp segments)
#pragma unroll
        for (int n = 0; n < 16; n++) {
            int g = gb | (n << 4);
            float2 a = w[n];
            __stcs(&or2[g], make_float2(a.x * sc, a.y * sc));
        }
    }
}

extern "C" void kernel_launch(void* const* d_in, const int* in_sizes, int n_in,
                              void* d_out, int out_size)
{
    const float* x     = (const float*)d_in[0];
    const float* scale = (const float*)d_in[1];
    float* out         = (float*)d_out;

    const int rows = in_sizes[0] / FWHT_N;

    fwht4096_kernel<<<rows, FWHT_THREADS>>>(x, scale, out);
}

// round 14
// speedup vs baseline: 1.0138x; 1.0138x over previous
#include <cuda_runtime.h>
#include <cstdint>

// FWHT over rows of length 4096: H4096 = H2^{⊗12}.  FINAL.
// 128 threads/CTA, 32 elements/thread, one row per CTA.
// Rounds: A = bits {0,1,9,10,11} (register, from 8 coalesced LDG.128),
//         B = bits {2,3,4}   (float4-granular smem exchange),
//         C = bits {5,6,7,8} (float2-granular smem exchange), then store.
// Swizzle on float4-index F' = F ^ ((F>>3)&7): conflict-free for all three
// smem patterns (verified per 8/16-lane phase), alignment-preserving.
// __launch_bounds__(128, 10): 48 regs / 10 CTAs/SM — best measured *bench*
// wall-clock (80.35us). The 56-reg/9-CTA variant is marginally faster in
// isolated ncu single-launch timing but consistently ~1.7us slower under
// the harness's back-to-back graph-replay timing (wave-transition overlap
// favors the higher-occupancy config). 40-reg cap is a cliff: load-stream
// serialization, DRAM 79%->64%.
// Converged at the B300 LTS path-independent throughput cap (~6.3 TB/s)
// for this mixed touch-once read+write stream.

#define FWHT_N 4096
#define FWHT_THREADS 128

// physical float4 index
__device__ __forceinline__ int swz4(int F) { return F ^ ((F >> 3) & 7); }

__device__ __forceinline__ float4 v4add(float4 a, float4 b) {
    return make_float4(a.x + b.x, a.y + b.y, a.z + b.z, a.w + b.w);
}
__device__ __forceinline__ float4 v4sub(float4 a, float4 b) {
    return make_float4(a.x - b.x, a.y - b.y, a.z - b.z, a.w - b.w);
}

// H8 butterfly across 8 float4 registers (componentwise).
__device__ __forceinline__ void fwht_h8_vec(float4* v) {
#pragma unroll
    for (int h = 1; h < 8; h <<= 1) {
#pragma unroll
        for (int s = 0; s < 8; s += 2 * h) {
#pragma unroll
            for (int k = 0; k < h; k++) {
                float4 a = v[s + k];
                float4 b = v[s + k + h];
                v[s + k]     = v4add(a, b);
                v[s + k + h] = v4sub(a, b);
            }
        }
    }
}

// H4 inside one float4 (element bits {0,1}).
__device__ __forceinline__ float4 fwht_h4_in(float4 a) {
    float x0 = a.x + a.y, x1 = a.x - a.y;
    float x2 = a.z + a.w, x3 = a.z - a.w;
    return make_float4(x0 + x2, x1 + x3, x0 - x2, x1 - x3);
}

__global__ void __launch_bounds__(FWHT_THREADS, 10)
fwht4096_kernel(const float* __restrict__ x,
                const float* __restrict__ scale,
                float* __restrict__ out)
{
    __shared__ float4 S4[FWHT_N / 4];
    float2* S2 = reinterpret_cast<float2*>(S4);

    const int row = blockIdx.x;
    const int t   = threadIdx.x;   // 0..127

    const float4* xr  = reinterpret_cast<const float4*>(x)  + (size_t)row * (FWHT_N / 4);
    float2*       or2 = reinterpret_cast<float2*>(out)      + (size_t)row * (FWHT_N / 2);

    float4 v[8];

    // ---- load: v[j] = x[row, 512j + 4t .. +3]   (8 coalesced LDG.128)
    // elem i = 4t + 512j + k : k->bits{0,1}, t->bits{2..8}, j->bits{9,10,11}
#pragma unroll
    for (int j = 0; j < 8; j++)
        v[j] = __ldcs(&xr[128 * j + t]);

    // ---- round A: H8 across j (bits 9..11) ⊗ H4 in-vector (bits 0,1)
    fwht_h8_vec(v);
#pragma unroll
    for (int j = 0; j < 8; j++)
        v[j] = fwht_h4_in(v[j]);

    // ---- exchange 1: logical float4-idx F = t + 128j
#pragma unroll
    for (int j = 0; j < 8; j++)
        S4[swz4(t + 128 * j)] = v[j];
    __syncthreads();

    // ---- round B: H8 over elem bits {2,3,4}
    // logical F = m | ((t&7)<<3) | ((t>>3)<<6), m = elem bits {2,3,4}
    {
        const int Fb = ((t & 7) << 3) | ((t >> 3) << 6);
#pragma unroll
        for (int m = 0; m < 8; m++)
            v[m] = S4[swz4(Fb | m)];

        fwht_h8_vec(v);   // butterfly across m

#pragma unroll
        for (int m = 0; m < 8; m++)
            S4[swz4(Fb | m)] = v[m];
    }
    __syncthreads();

    // ---- round C: H16 over elem bits {5,6,7,8} at float2 granularity
    // logical float2-idx g = (n<<4) | (t&15) | ((t>>4)<<8), n = elem bits {5..8}
    {
        const int gb = (t & 15) | ((t >> 4) << 8);
        float2 w[16];
#pragma unroll
        for (int n = 0; n < 16; n++) {
            int g = gb | (n << 4);
            w[n] = S2[(swz4(g >> 1) << 1) | (g & 1)];
        }

#pragma unroll
        for (int h = 1; h < 16; h <<= 1) {
#pragma unroll
            for (int s = 0; s < 16; s += 2 * h) {
#pragma unroll
                for (int k = 0; k < h; k++) {
                    float2 a = w[s + k];
                    float2 b = w[s + k + h];
                    w[s + k]     = make_float2(a.x + b.x, a.y + b.y);
                    w[s + k + h] = make_float2(a.x - b.x, a.y - b.y);
                }
            }
        }

        const float sc = *scale;
        // store: global float2-idx g (coalesced per-warp segments)
#pragma unroll
        for (int n = 0; n < 16; n++) {
            int g = gb | (n << 4);
            float2 a = w[n];
            __stcs(&or2[g], make_float2(a.x * sc, a.y * sc));
        }
    }
}

extern "C" void kernel_launch(void* const* d_in, const int* in_sizes, int n_in,
                              void* d_out, int out_size)
{
    const float* x     = (const float*)d_in[0];
    const float* scale = (const float*)d_in[1];
    float* out         = (float*)d_out;

    const int rows = in_sizes[0] / FWHT_N;

    fwht4096_kernel<<<rows, FWHT_THREADS>>>(x, scale, out);
}